// round 1
// baseline (speedup 1.0000x reference)
#include <cuda_runtime.h>

#define B_  2
#define L_  2048
#define D_  1024
#define H_  16
#define DH_ 64
#define BL_ (B_ * L_)

// ---------------- scratch (device globals; no allocs allowed) ----------------
__device__ float g_q[BL_ * D_];
__device__ float g_k[BL_ * D_];
__device__ float g_v[BL_ * D_];
__device__ float g_o[BL_ * D_];

// Exactly-rounded inv_freq[p] = 10000^(-p/32) = 10^(-p/8), p = 0..31
__device__ const float g_invfreq[32] = {
    1.0f,
    0.7498942093324559f,
    0.5623413251903491f,
    0.4216965034285823f,
    0.31622776601683794f,
    0.2371373705661655f,
    0.1778279410038923f,
    0.13335214321633237f,
    0.1f,
    0.07498942093324559f,
    0.05623413251903491f,
    0.04216965034285823f,
    0.031622776601683794f,
    0.02371373705661655f,
    0.01778279410038923f,
    0.013335214321633237f,
    0.01f,
    0.007498942093324559f,
    0.005623413251903491f,
    0.004216965034285823f,
    0.0031622776601683794f,
    0.002371373705661655f,
    0.001778279410038923f,
    0.0013335214321633237f,
    0.001f,
    0.0007498942093324559f,
    0.0005623413251903491f,
    0.0004216965034285823f,
    0.00031622776601683794f,
    0.0002371373705661655f,
    0.0001778279410038923f,
    0.00013335214321633237f
};

// ---------------------------------------------------------------------------
// GEMM (NT): C[M,N] = A[M,K] * W[N,K]^T.  M % 128 == 0, N % 128 == 0, K % 16 == 0
// 128x128 block tile, K-tile 16, 256 threads, 8x8 per thread. FFMA-bound.
// ---------------------------------------------------------------------------
__global__ __launch_bounds__(256) void gemm_nt(const float* __restrict__ A,
                                               const float* __restrict__ W,
                                               float* __restrict__ C,
                                               int M, int N, int K)
{
    __shared__ float As[16][128];   // [kk][m]
    __shared__ float Bs[16][128];   // [kk][n]

    const int tid = threadIdx.x;
    const int tx  = tid & 15;
    const int ty  = tid >> 4;
    const int m0  = blockIdx.y * 128;
    const int n0  = blockIdx.x * 128;

    const int lrow = tid >> 2;             // 0..63
    const int lcg  = (tid & 3) << 2;       // 0,4,8,12

    const float* aptr0 = A + (size_t)(m0 + lrow)      * K + lcg;
    const float* aptr1 = A + (size_t)(m0 + lrow + 64) * K + lcg;
    const float* wptr0 = W + (size_t)(n0 + lrow)      * K + lcg;
    const float* wptr1 = W + (size_t)(n0 + lrow + 64) * K + lcg;

    float acc[8][8];
#pragma unroll
    for (int i = 0; i < 8; i++)
#pragma unroll
        for (int j = 0; j < 8; j++) acc[i][j] = 0.0f;

    float4 a0 = *(const float4*)aptr0;
    float4 a1 = *(const float4*)aptr1;
    float4 b0 = *(const float4*)wptr0;
    float4 b1 = *(const float4*)wptr1;

    for (int k0 = 0; k0 < K; k0 += 16) {
        __syncthreads();
        As[lcg + 0][lrow]      = a0.x;
        As[lcg + 1][lrow]      = a0.y;
        As[lcg + 2][lrow]      = a0.z;
        As[lcg + 3][lrow]      = a0.w;
        As[lcg + 0][lrow + 64] = a1.x;
        As[lcg + 1][lrow + 64] = a1.y;
        As[lcg + 2][lrow + 64] = a1.z;
        As[lcg + 3][lrow + 64] = a1.w;
        Bs[lcg + 0][lrow]      = b0.x;
        Bs[lcg + 1][lrow]      = b0.y;
        Bs[lcg + 2][lrow]      = b0.z;
        Bs[lcg + 3][lrow]      = b0.w;
        Bs[lcg + 0][lrow + 64] = b1.x;
        Bs[lcg + 1][lrow + 64] = b1.y;
        Bs[lcg + 2][lrow + 64] = b1.z;
        Bs[lcg + 3][lrow + 64] = b1.w;
        __syncthreads();

        if (k0 + 16 < K) {
            a0 = *(const float4*)(aptr0 + k0 + 16);
            a1 = *(const float4*)(aptr1 + k0 + 16);
            b0 = *(const float4*)(wptr0 + k0 + 16);
            b1 = *(const float4*)(wptr1 + k0 + 16);
        }

#pragma unroll
        for (int kk = 0; kk < 16; kk++) {
            float av[8], bv[8];
            *(float4*)&av[0] = *(const float4*)&As[kk][ty * 8 + 0];
            *(float4*)&av[4] = *(const float4*)&As[kk][ty * 8 + 4];
            *(float4*)&bv[0] = *(const float4*)&Bs[kk][tx * 8 + 0];
            *(float4*)&bv[4] = *(const float4*)&Bs[kk][tx * 8 + 4];
#pragma unroll
            for (int i = 0; i < 8; i++)
#pragma unroll
                for (int j = 0; j < 8; j++)
                    acc[i][j] += av[i] * bv[j];
        }
    }

#pragma unroll
    for (int i = 0; i < 8; i++) {
        float* cp = C + (size_t)(m0 + ty * 8 + i) * N + n0 + tx * 8;
        *(float4*)(cp + 0) = *(float4*)&acc[i][0];
        *(float4*)(cp + 4) = *(float4*)&acc[i][4];
    }
}

// ---------------------------------------------------------------------------
// RoPE in-place on Q and K.  Layout: [bl][e], e = h*64 + dh; pairs (2p, 2p+1).
// One thread per pair; pairs are contiguous -> float2 vector access.
// ---------------------------------------------------------------------------
__global__ __launch_bounds__(256) void rope_kernel(float* __restrict__ q,
                                                   float* __restrict__ k,
                                                   const int* __restrict__ pos)
{
    const int t = blockIdx.x * 256 + threadIdx.x;
    if (t >= BL_ * (D_ / 2)) return;

    const int bl = t >> 9;           // / (D/2 = 512)
    const int e2 = t & 511;          // pair index within row
    const int p  = e2 & 31;          // pair within head (DH/2 = 32)
    const int l  = bl & (L_ - 1);

    const float ang = (float)pos[l] * g_invfreq[p];
    float s, c;
    sincosf(ang, &s, &c);

    float2* q2 = (float2*)q;
    float2* k2 = (float2*)k;

    float2 v = q2[t];
    q2[t] = make_float2(v.x * c - v.y * s, v.x * s + v.y * c);
    v = k2[t];
    k2[t] = make_float2(v.x * c - v.y * s, v.x * s + v.y * c);
}

// ---------------------------------------------------------------------------
// Flash attention, causal. Per block: one (b, h, q-tile of 64 rows).
// Q/K in smem transposed [d][row] for float4 operand reads; V natural [tok][d].
// KPs buffer is reused: K tile during S-phase, P tile during PV-phase.
// 256 threads = 16x16, each thread 4x4 of the 64x64 S / O tiles.
// ---------------------------------------------------------------------------
__global__ __launch_bounds__(256) void attn_kernel(const float* __restrict__ Q,
                                                   const float* __restrict__ Kp,
                                                   const float* __restrict__ Vp,
                                                   float* __restrict__ O)
{
    __shared__ float Qs[64 * 64];    // [d][row]
    __shared__ float KPs[64 * 64];   // K: [d][col]  /  P: [row][col]
    __shared__ float Vs[64 * 64];    // [tok][d]

    const int tid = threadIdx.x;
    const int tx  = tid & 15;
    const int ty  = tid >> 4;
    const int qt  = blockIdx.x;
    const int h   = blockIdx.y;
    const int b   = blockIdx.z;
    const int q0  = qt * 64;

    const int lrow = tid >> 2;            // 0..63
    const int lc16 = (tid & 3) * 16;      // 0,16,32,48

    // ---- load Q tile, transposed into smem ----
    {
        const float* src = Q + (size_t)(b * L_ + q0 + lrow) * D_ + h * DH_ + lc16;
#pragma unroll
        for (int c = 0; c < 16; c += 4) {
            float4 v = *(const float4*)(src + c);
            Qs[(lc16 + c + 0) * 64 + lrow] = v.x;
            Qs[(lc16 + c + 1) * 64 + lrow] = v.y;
            Qs[(lc16 + c + 2) * 64 + lrow] = v.z;
            Qs[(lc16 + c + 3) * 64 + lrow] = v.w;
        }
    }

    float m_run[4], l_run[4], acc[4][4];
#pragma unroll
    for (int i = 0; i < 4; i++) {
        m_run[i] = -1e30f;
        l_run[i] = 0.0f;
#pragma unroll
        for (int j = 0; j < 4; j++) acc[i][j] = 0.0f;
    }

    for (int kt = 0; kt <= qt; kt++) {
        const int k0 = kt * 64;

        __syncthreads();   // prev PV reads done (also covers Qs store, iter 0)

        // ---- load K (transposed) and V (natural) tiles ----
        {
            const float* ks = Kp + (size_t)(b * L_ + k0 + lrow) * D_ + h * DH_ + lc16;
            const float* vs = Vp + (size_t)(b * L_ + k0 + lrow) * D_ + h * DH_ + lc16;
#pragma unroll
            for (int c = 0; c < 16; c += 4) {
                float4 kv = *(const float4*)(ks + c);
                KPs[(lc16 + c + 0) * 64 + lrow] = kv.x;
                KPs[(lc16 + c + 1) * 64 + lrow] = kv.y;
                KPs[(lc16 + c + 2) * 64 + lrow] = kv.z;
                KPs[(lc16 + c + 3) * 64 + lrow] = kv.w;
                float4 vv = *(const float4*)(vs + c);
                *(float4*)&Vs[lrow * 64 + lc16 + c] = vv;
            }
        }
        __syncthreads();

        // ---- S = Q K^T ----
        float s[4][4];
#pragma unroll
        for (int i = 0; i < 4; i++)
#pragma unroll
            for (int j = 0; j < 4; j++) s[i][j] = 0.0f;

#pragma unroll 8
        for (int kk = 0; kk < 64; kk++) {
            float qv[4], kv[4];
            *(float4*)qv = *(const float4*)&Qs[kk * 64 + ty * 4];
            *(float4*)kv = *(const float4*)&KPs[kk * 64 + tx * 4];
#pragma unroll
            for (int i = 0; i < 4; i++)
#pragma unroll
                for (int j = 0; j < 4; j++)
                    s[i][j] += qv[i] * kv[j];
        }

        // ---- scale + causal mask (only diagonal tile can mask) ----
        const bool diag = (kt == qt);
#pragma unroll
        for (int i = 0; i < 4; i++)
#pragma unroll
            for (int j = 0; j < 4; j++) {
                float v = s[i][j] * 0.125f;
                if (diag && (tx * 4 + j > ty * 4 + i)) v = -1e30f;
                s[i][j] = v;
            }

        // ---- online softmax: row max / sum across the 16 tx lanes ----
        float mnew[4], corr[4];
#pragma unroll
        for (int i = 0; i < 4; i++) {
            float mx = fmaxf(fmaxf(s[i][0], s[i][1]), fmaxf(s[i][2], s[i][3]));
#pragma unroll
            for (int o = 8; o > 0; o >>= 1)
                mx = fmaxf(mx, __shfl_xor_sync(0xffffffffu, mx, o, 16));
            mnew[i] = fmaxf(m_run[i], mx);
            corr[i] = __expf(m_run[i] - mnew[i]);
        }

        __syncthreads();   // everyone done reading KPs as K before P overwrite

#pragma unroll
        for (int i = 0; i < 4; i++) {
            float ps = 0.0f;
#pragma unroll
            for (int j = 0; j < 4; j++) {
                float p = __expf(s[i][j] - mnew[i]);
                s[i][j] = p;
                ps += p;
            }
#pragma unroll
            for (int o = 8; o > 0; o >>= 1)
                ps += __shfl_xor_sync(0xffffffffu, ps, o, 16);
            l_run[i] = l_run[i] * corr[i] + ps;
            m_run[i] = mnew[i];
#pragma unroll
            for (int j = 0; j < 4; j++) acc[i][j] *= corr[i];
            *(float4*)&KPs[(ty * 4 + i) * 64 + tx * 4] = *(float4*)&s[i][0];
        }
        __syncthreads();   // P visible

        // ---- O += P @ V ----
#pragma unroll 8
        for (int kk = 0; kk < 64; kk++) {
            float vv[4];
            *(float4*)vv = *(const float4*)&Vs[kk * 64 + tx * 4];
#pragma unroll
            for (int i = 0; i < 4; i++) {
                float p = KPs[(ty * 4 + i) * 64 + kk];
#pragma unroll
                for (int j = 0; j < 4; j++) acc[i][j] += p * vv[j];
            }
        }
    }

    // ---- normalize + store O in (b, l, h*64+dh) layout ----
    float* op = O + (size_t)(b * L_ + q0) * D_ + h * DH_;
#pragma unroll
    for (int i = 0; i < 4; i++) {
        float inv = 1.0f / l_run[i];
        float o4[4];
#pragma unroll
        for (int j = 0; j < 4; j++) o4[j] = acc[i][j] * inv;
        *(float4*)(op + (ty * 4 + i) * D_ + tx * 4) = *(float4*)o4;
    }
}

// ---------------------------------------------------------------------------
extern "C" void kernel_launch(void* const* d_in, const int* in_sizes, int n_in,
                              void* d_out, int out_size)
{
    const float* x   = (const float*)d_in[0];
    const float* Wq  = (const float*)d_in[1];
    const float* Wk  = (const float*)d_in[2];
    const float* Wv  = (const float*)d_in[3];
    const float* Wo  = (const float*)d_in[4];
    const int*   pos = (const int*)  d_in[5];
    float* out = (float*)d_out;

    float *q_ptr, *k_ptr, *v_ptr, *o_ptr;
    cudaGetSymbolAddress((void**)&q_ptr, g_q);
    cudaGetSymbolAddress((void**)&k_ptr, g_k);
    cudaGetSymbolAddress((void**)&v_ptr, g_v);
    cudaGetSymbolAddress((void**)&o_ptr, g_o);

    dim3 ggrid(D_ / 128, BL_ / 128);   // (8, 32)

    gemm_nt<<<ggrid, 256>>>(x, Wq, q_ptr, BL_, D_, D_);
    gemm_nt<<<ggrid, 256>>>(x, Wk, k_ptr, BL_, D_, D_);
    gemm_nt<<<ggrid, 256>>>(x, Wv, v_ptr, BL_, D_, D_);

    rope_kernel<<<(BL_ * (D_ / 2)) / 256, 256>>>(q_ptr, k_ptr, pos);

    attn_kernel<<<dim3(L_ / 64, H_, B_), 256>>>(q_ptr, k_ptr, v_ptr, o_ptr);

    gemm_nt<<<ggrid, 256>>>(o_ptr, Wo, out, BL_, D_, D_);
}

// round 2
// speedup vs baseline: 1.0401x; 1.0401x over previous
#include <cuda_runtime.h>

#define B_  2
#define L_  2048
#define D_  1024
#define H_  16
#define DH_ 64
#define BL_ (B_ * L_)

typedef unsigned long long ull;

// ---- f32x2 packed-pair helpers (FFMA2 path; ptxas never emits this from C++) ----
__device__ __forceinline__ ull pk2(float lo, float hi) {
    ull r; asm("mov.b64 %0, {%1, %2};" : "=l"(r) : "f"(lo), "f"(hi)); return r;
}
__device__ __forceinline__ void upk2(ull v, float& lo, float& hi) {
    asm("mov.b64 {%0, %1}, %2;" : "=f"(lo), "=f"(hi) : "l"(v));
}
__device__ __forceinline__ ull fma2_(ull a, ull b, ull c) {
    ull d; asm("fma.rn.f32x2 %0, %1, %2, %3;" : "=l"(d) : "l"(a), "l"(b), "l"(c)); return d;
}
__device__ __forceinline__ ull mul2_(ull a, ull b) {
    ull d; asm("mul.rn.f32x2 %0, %1, %2;" : "=l"(d) : "l"(a), "l"(b)); return d;
}

// ---------------- scratch (device globals; no allocs allowed) ----------------
__device__ float g_q[BL_ * D_];
__device__ float g_k[BL_ * D_];
__device__ float g_v[BL_ * D_];
__device__ float g_o[BL_ * D_];

// Exactly-rounded inv_freq[p] = 10000^(-p/32) = 10^(-p/8), p = 0..31
__device__ const float g_invfreq[32] = {
    1.0f, 0.7498942093324559f, 0.5623413251903491f, 0.4216965034285823f,
    0.31622776601683794f, 0.2371373705661655f, 0.1778279410038923f, 0.13335214321633237f,
    0.1f, 0.07498942093324559f, 0.05623413251903491f, 0.04216965034285823f,
    0.031622776601683794f, 0.02371373705661655f, 0.01778279410038923f, 0.013335214321633237f,
    0.01f, 0.007498942093324559f, 0.005623413251903491f, 0.004216965034285823f,
    0.0031622776601683794f, 0.002371373705661655f, 0.001778279410038923f, 0.0013335214321633237f,
    0.001f, 0.0007498942093324559f, 0.0005623413251903491f, 0.0004216965034285823f,
    0.00031622776601683794f, 0.0002371373705661655f, 0.0001778279410038923f, 0.00013335214321633237f
};

// ---------------------------------------------------------------------------
// GEMM body (NT): C[4096,1024] = A[4096,1024] * W[1024,1024]^T
// 128x128 tile, K-tile 16, 256 threads, 8x8 per thread via f32x2 FFMA2.
// ---------------------------------------------------------------------------
__device__ __forceinline__ void gemm_body(const float* __restrict__ A,
                                          const float* __restrict__ W,
                                          float* __restrict__ C)
{
    __shared__ float As[16][128];   // [kk][m]
    __shared__ float Bs[16][128];   // [kk][n]

    const int tid = threadIdx.x;
    const int tx  = tid & 15;
    const int ty  = tid >> 4;
    const int m0  = blockIdx.y * 128;
    const int n0  = blockIdx.x * 128;

    const int lrow = tid >> 2;             // 0..63
    const int lcg  = (tid & 3) << 2;       // 0,4,8,12

    const float* aptr0 = A + (size_t)(m0 + lrow)      * D_ + lcg;
    const float* aptr1 = A + (size_t)(m0 + lrow + 64) * D_ + lcg;
    const float* wptr0 = W + (size_t)(n0 + lrow)      * D_ + lcg;
    const float* wptr1 = W + (size_t)(n0 + lrow + 64) * D_ + lcg;

    ull acc2[8][4];
#pragma unroll
    for (int i = 0; i < 8; i++)
#pragma unroll
        for (int j = 0; j < 4; j++) acc2[i][j] = 0ull;

    float4 a0 = *(const float4*)aptr0;
    float4 a1 = *(const float4*)aptr1;
    float4 b0 = *(const float4*)wptr0;
    float4 b1 = *(const float4*)wptr1;

    for (int k0 = 0; k0 < D_; k0 += 16) {
        __syncthreads();
        As[lcg + 0][lrow]      = a0.x;
        As[lcg + 1][lrow]      = a0.y;
        As[lcg + 2][lrow]      = a0.z;
        As[lcg + 3][lrow]      = a0.w;
        As[lcg + 0][lrow + 64] = a1.x;
        As[lcg + 1][lrow + 64] = a1.y;
        As[lcg + 2][lrow + 64] = a1.z;
        As[lcg + 3][lrow + 64] = a1.w;
        Bs[lcg + 0][lrow]      = b0.x;
        Bs[lcg + 1][lrow]      = b0.y;
        Bs[lcg + 2][lrow]      = b0.z;
        Bs[lcg + 3][lrow]      = b0.w;
        Bs[lcg + 0][lrow + 64] = b1.x;
        Bs[lcg + 1][lrow + 64] = b1.y;
        Bs[lcg + 2][lrow + 64] = b1.z;
        Bs[lcg + 3][lrow + 64] = b1.w;
        __syncthreads();

        if (k0 + 16 < D_) {
            a0 = *(const float4*)(aptr0 + k0 + 16);
            a1 = *(const float4*)(aptr1 + k0 + 16);
            b0 = *(const float4*)(wptr0 + k0 + 16);
            b1 = *(const float4*)(wptr1 + k0 + 16);
        }

#pragma unroll
        for (int kk = 0; kk < 16; kk++) {
            float4 avA = *(const float4*)&As[kk][ty * 8 + 0];
            float4 avB = *(const float4*)&As[kk][ty * 8 + 4];
            float4 bvA = *(const float4*)&Bs[kk][tx * 8 + 0];
            float4 bvB = *(const float4*)&Bs[kk][tx * 8 + 4];

            ull bp[4];
            bp[0] = pk2(bvA.x, bvA.y);
            bp[1] = pk2(bvA.z, bvA.w);
            bp[2] = pk2(bvB.x, bvB.y);
            bp[3] = pk2(bvB.z, bvB.w);

            float av[8] = {avA.x, avA.y, avA.z, avA.w, avB.x, avB.y, avB.z, avB.w};
#pragma unroll
            for (int i = 0; i < 8; i++) {
                ull ai = pk2(av[i], av[i]);
#pragma unroll
                for (int j = 0; j < 4; j++)
                    acc2[i][j] = fma2_(ai, bp[j], acc2[i][j]);
            }
        }
    }

#pragma unroll
    for (int i = 0; i < 8; i++) {
        float c[8];
#pragma unroll
        for (int j = 0; j < 4; j++) upk2(acc2[i][j], c[2 * j], c[2 * j + 1]);
        float* cp = C + (size_t)(m0 + ty * 8 + i) * D_ + n0 + tx * 8;
        *(float4*)(cp + 0) = *(float4*)&c[0];
        *(float4*)(cp + 4) = *(float4*)&c[4];
    }
}

// Fused QKV: blockIdx.z selects which projection this block computes.
__global__ __launch_bounds__(256) void gemm_qkv(const float* __restrict__ x,
                                                const float* __restrict__ Wq,
                                                const float* __restrict__ Wk,
                                                const float* __restrict__ Wv,
                                                float* __restrict__ q,
                                                float* __restrict__ k,
                                                float* __restrict__ v)
{
    const int z = blockIdx.z;
    const float* W = (z == 0) ? Wq : (z == 1) ? Wk : Wv;
    float*       C = (z == 0) ? q  : (z == 1) ? k  : v;
    gemm_body(x, W, C);
}

__global__ __launch_bounds__(256) void gemm_one(const float* __restrict__ A,
                                                const float* __restrict__ W,
                                                float* __restrict__ C)
{
    gemm_body(A, W, C);
}

// ---------------------------------------------------------------------------
// RoPE in-place on Q and K.
// ---------------------------------------------------------------------------
__global__ __launch_bounds__(256) void rope_kernel(float* __restrict__ q,
                                                   float* __restrict__ k,
                                                   const int* __restrict__ pos)
{
    const int t = blockIdx.x * 256 + threadIdx.x;
    if (t >= BL_ * (D_ / 2)) return;

    const int bl = t >> 9;
    const int e2 = t & 511;
    const int p  = e2 & 31;
    const int l  = bl & (L_ - 1);

    const float ang = (float)pos[l] * g_invfreq[p];
    float s, c;
    sincosf(ang, &s, &c);

    float2* q2 = (float2*)q;
    float2* k2 = (float2*)k;

    float2 v = q2[t];
    q2[t] = make_float2(v.x * c - v.y * s, v.x * s + v.y * c);
    v = k2[t];
    k2[t] = make_float2(v.x * c - v.y * s, v.x * s + v.y * c);
}

// ---------------------------------------------------------------------------
// Flash attention, causal, f32x2 inner loops.
// Per block: one (b, h, q-tile of 64 rows). 256 threads = 16x16, 4x4/thread.
// ---------------------------------------------------------------------------
__global__ __launch_bounds__(256) void attn_kernel(const float* __restrict__ Q,
                                                   const float* __restrict__ Kp,
                                                   const float* __restrict__ Vp,
                                                   float* __restrict__ O)
{
    __shared__ float Qs[64 * 64];    // [d][row]
    __shared__ float KPs[64 * 64];   // K: [d][col]  /  P: [row][col]
    __shared__ float Vs[64 * 64];    // [tok][d]

    const int tid = threadIdx.x;
    const int tx  = tid & 15;
    const int ty  = tid >> 4;
    const int qt  = blockIdx.x;
    const int h   = blockIdx.y;
    const int b   = blockIdx.z;
    const int q0  = qt * 64;

    const int lrow = tid >> 2;            // 0..63
    const int lc16 = (tid & 3) * 16;      // 0,16,32,48

    // ---- load Q tile, transposed into smem ----
    {
        const float* src = Q + (size_t)(b * L_ + q0 + lrow) * D_ + h * DH_ + lc16;
#pragma unroll
        for (int c = 0; c < 16; c += 4) {
            float4 v = *(const float4*)(src + c);
            Qs[(lc16 + c + 0) * 64 + lrow] = v.x;
            Qs[(lc16 + c + 1) * 64 + lrow] = v.y;
            Qs[(lc16 + c + 2) * 64 + lrow] = v.z;
            Qs[(lc16 + c + 3) * 64 + lrow] = v.w;
        }
    }

    float m_run[4], l_run[4];
    ull acc2[4][2];
#pragma unroll
    for (int i = 0; i < 4; i++) {
        m_run[i] = -1e30f;
        l_run[i] = 0.0f;
        acc2[i][0] = 0ull;
        acc2[i][1] = 0ull;
    }

    for (int kt = 0; kt <= qt; kt++) {
        const int k0 = kt * 64;

        __syncthreads();   // prev PV reads done (also covers Qs store, iter 0)

        // ---- load K (transposed) and V (natural) tiles ----
        {
            const float* ks = Kp + (size_t)(b * L_ + k0 + lrow) * D_ + h * DH_ + lc16;
            const float* vs = Vp + (size_t)(b * L_ + k0 + lrow) * D_ + h * DH_ + lc16;
#pragma unroll
            for (int c = 0; c < 16; c += 4) {
                float4 kv = *(const float4*)(ks + c);
                KPs[(lc16 + c + 0) * 64 + lrow] = kv.x;
                KPs[(lc16 + c + 1) * 64 + lrow] = kv.y;
                KPs[(lc16 + c + 2) * 64 + lrow] = kv.z;
                KPs[(lc16 + c + 3) * 64 + lrow] = kv.w;
                float4 vv = *(const float4*)(vs + c);
                *(float4*)&Vs[lrow * 64 + lc16 + c] = vv;
            }
        }
        __syncthreads();

        // ---- S = Q K^T (f32x2) ----
        ull s2[4][2];
#pragma unroll
        for (int i = 0; i < 4; i++) { s2[i][0] = 0ull; s2[i][1] = 0ull; }

#pragma unroll 8
        for (int kk = 0; kk < 64; kk++) {
            float4 q4 = *(const float4*)&Qs[kk * 64 + ty * 4];
            float4 k4 = *(const float4*)&KPs[kk * 64 + tx * 4];
            ull k01 = pk2(k4.x, k4.y);
            ull k23 = pk2(k4.z, k4.w);
            float qv[4] = {q4.x, q4.y, q4.z, q4.w};
#pragma unroll
            for (int i = 0; i < 4; i++) {
                ull qi = pk2(qv[i], qv[i]);
                s2[i][0] = fma2_(qi, k01, s2[i][0]);
                s2[i][1] = fma2_(qi, k23, s2[i][1]);
            }
        }

        // ---- unpack, scale + causal mask ----
        float s[4][4];
        const bool diag = (kt == qt);
#pragma unroll
        for (int i = 0; i < 4; i++) {
            upk2(s2[i][0], s[i][0], s[i][1]);
            upk2(s2[i][1], s[i][2], s[i][3]);
#pragma unroll
            for (int j = 0; j < 4; j++) {
                float v = s[i][j] * 0.125f;
                if (diag && (tx * 4 + j > ty * 4 + i)) v = -1e30f;
                s[i][j] = v;
            }
        }

        // ---- online softmax ----
        float mnew[4], corr[4];
#pragma unroll
        for (int i = 0; i < 4; i++) {
            float mx = fmaxf(fmaxf(s[i][0], s[i][1]), fmaxf(s[i][2], s[i][3]));
#pragma unroll
            for (int o = 8; o > 0; o >>= 1)
                mx = fmaxf(mx, __shfl_xor_sync(0xffffffffu, mx, o, 16));
            mnew[i] = fmaxf(m_run[i], mx);
            corr[i] = __expf(m_run[i] - mnew[i]);
        }

        __syncthreads();   // everyone done reading KPs as K before P overwrite

#pragma unroll
        for (int i = 0; i < 4; i++) {
            float ps = 0.0f;
#pragma unroll
            for (int j = 0; j < 4; j++) {
                float p = __expf(s[i][j] - mnew[i]);
                s[i][j] = p;
                ps += p;
            }
#pragma unroll
            for (int o = 8; o > 0; o >>= 1)
                ps += __shfl_xor_sync(0xffffffffu, ps, o, 16);
            l_run[i] = l_run[i] * corr[i] + ps;
            m_run[i] = mnew[i];
            ull cp = pk2(corr[i], corr[i]);
            acc2[i][0] = mul2_(cp, acc2[i][0]);
            acc2[i][1] = mul2_(cp, acc2[i][1]);
            *(float4*)&KPs[(ty * 4 + i) * 64 + tx * 4] = *(float4*)&s[i][0];
        }
        __syncthreads();   // P visible

        // ---- O += P @ V (f32x2, P vectorized along kk) ----
#pragma unroll 4
        for (int kk0 = 0; kk0 < 64; kk0 += 4) {
            float4 p4[4];
#pragma unroll
            for (int i = 0; i < 4; i++)
                p4[i] = *(const float4*)&KPs[(ty * 4 + i) * 64 + kk0];
#pragma unroll
            for (int kx = 0; kx < 4; kx++) {
                float4 v4 = *(const float4*)&Vs[(kk0 + kx) * 64 + tx * 4];
                ull v01 = pk2(v4.x, v4.y);
                ull v23 = pk2(v4.z, v4.w);
#pragma unroll
                for (int i = 0; i < 4; i++) {
                    float p = (kx == 0) ? p4[i].x : (kx == 1) ? p4[i].y
                            : (kx == 2) ? p4[i].z : p4[i].w;
                    ull pp = pk2(p, p);
                    acc2[i][0] = fma2_(pp, v01, acc2[i][0]);
                    acc2[i][1] = fma2_(pp, v23, acc2[i][1]);
                }
            }
        }
    }

    // ---- normalize + store O ----
    float* op = O + (size_t)(b * L_ + q0) * D_ + h * DH_;
#pragma unroll
    for (int i = 0; i < 4; i++) {
        float inv = 1.0f / l_run[i];
        float o4[4];
        upk2(acc2[i][0], o4[0], o4[1]);
        upk2(acc2[i][1], o4[2], o4[3]);
#pragma unroll
        for (int j = 0; j < 4; j++) o4[j] *= inv;
        *(float4*)(op + (ty * 4 + i) * D_ + tx * 4) = *(float4*)o4;
    }
}

// ---------------------------------------------------------------------------
extern "C" void kernel_launch(void* const* d_in, const int* in_sizes, int n_in,
                              void* d_out, int out_size)
{
    const float* x   = (const float*)d_in[0];
    const float* Wq  = (const float*)d_in[1];
    const float* Wk  = (const float*)d_in[2];
    const float* Wv  = (const float*)d_in[3];
    const float* Wo  = (const float*)d_in[4];
    const int*   pos = (const int*)  d_in[5];
    float* out = (float*)d_out;

    float *q_ptr, *k_ptr, *v_ptr, *o_ptr;
    cudaGetSymbolAddress((void**)&q_ptr, g_q);
    cudaGetSymbolAddress((void**)&k_ptr, g_k);
    cudaGetSymbolAddress((void**)&v_ptr, g_v);
    cudaGetSymbolAddress((void**)&o_ptr, g_o);

    dim3 qkv_grid(D_ / 128, BL_ / 128, 3);   // (8, 32, 3)
    gemm_qkv<<<qkv_grid, 256>>>(x, Wq, Wk, Wv, q_ptr, k_ptr, v_ptr);

    rope_kernel<<<(BL_ * (D_ / 2)) / 256, 256>>>(q_ptr, k_ptr, pos);

    attn_kernel<<<dim3(L_ / 64, H_, B_), 256>>>(q_ptr, k_ptr, v_ptr, o_ptr);

    dim3 ggrid(D_ / 128, BL_ / 128);
    gemm_one<<<ggrid, 256>>>(o_ptr, Wo, out);
}

// round 4
// speedup vs baseline: 1.6280x; 1.5653x over previous
#include <cuda_runtime.h>
#include <cuda_bf16.h>
#include <cstdint>

#define B_  2
#define L_  2048
#define D_  1024
#define H_  16
#define DH_ 64
#define BL_ (B_ * L_)

typedef unsigned long long ull;

// ============================ helpers ============================
__device__ __forceinline__ uint32_t smem_u32(const void* p) {
    uint32_t a;
    asm("{ .reg .u64 t; cvta.to.shared.u64 t, %1; cvt.u32.u64 %0, t; }" : "=r"(a) : "l"(p));
    return a;
}
#define SMEM_SWIZZLE_128B(x) ((x) ^ (((x) >> 3) & 0x70))

__device__ __forceinline__ void cp_async16(uint32_t dst, const void* src) {
    asm volatile("cp.async.ca.shared.global [%0], [%1], 16;" :: "r"(dst), "l"(src) : "memory");
}
#define CP_COMMIT() asm volatile("cp.async.commit_group;" ::: "memory")

__device__ __forceinline__ void ldm_x4(uint32_t* r, uint32_t addr) {
    asm volatile("ldmatrix.sync.aligned.m8n8.x4.shared.b16 {%0,%1,%2,%3}, [%4];"
        : "=r"(r[0]), "=r"(r[1]), "=r"(r[2]), "=r"(r[3]) : "r"(addr));
}

// D = A*B + D  (m16n8k16, bf16 in, fp32 accum)
__device__ __forceinline__ void mma16816(float* c, const uint32_t* a, const uint32_t* b) {
    asm volatile("mma.sync.aligned.m16n8k16.row.col.f32.bf16.bf16.f32 "
        "{%0,%1,%2,%3}, {%4,%5,%6,%7}, {%8,%9}, {%0,%1,%2,%3};"
        : "+f"(c[0]), "+f"(c[1]), "+f"(c[2]), "+f"(c[3])
        : "r"(a[0]), "r"(a[1]), "r"(a[2]), "r"(a[3]), "r"(b[0]), "r"(b[1]));
}

// ---- f32x2 packed-pair helpers (attention) ----
__device__ __forceinline__ ull pk2(float lo, float hi) {
    ull r; asm("mov.b64 %0, {%1, %2};" : "=l"(r) : "f"(lo), "f"(hi)); return r;
}
__device__ __forceinline__ void upk2(ull v, float& lo, float& hi) {
    asm("mov.b64 {%0, %1}, %2;" : "=f"(lo), "=f"(hi) : "l"(v));
}
__device__ __forceinline__ ull fma2_(ull a, ull b, ull c) {
    ull d; asm("fma.rn.f32x2 %0, %1, %2, %3;" : "=l"(d) : "l"(a), "l"(b), "l"(c)); return d;
}
__device__ __forceinline__ ull mul2_(ull a, ull b) {
    ull d; asm("mul.rn.f32x2 %0, %1, %2;" : "=l"(d) : "l"(a), "l"(b)); return d;
}

// ============================ scratch globals ============================
__device__ float g_q[BL_ * D_];
__device__ float g_k[BL_ * D_];
__device__ float g_v[BL_ * D_];
__device__ float g_o[BL_ * D_];
__device__ __nv_bfloat16 g_xhi[BL_ * D_];
__device__ __nv_bfloat16 g_xlo[BL_ * D_];
__device__ __nv_bfloat16 g_ohi[BL_ * D_];
__device__ __nv_bfloat16 g_olo[BL_ * D_];
__device__ __nv_bfloat16 g_whi[4 * D_ * D_];
__device__ __nv_bfloat16 g_wlo[4 * D_ * D_];

__device__ const float g_invfreq[32] = {
    1.0f, 0.7498942093324559f, 0.5623413251903491f, 0.4216965034285823f,
    0.31622776601683794f, 0.2371373705661655f, 0.1778279410038923f, 0.13335214321633237f,
    0.1f, 0.07498942093324559f, 0.05623413251903491f, 0.04216965034285823f,
    0.031622776601683794f, 0.02371373705661655f, 0.01778279410038923f, 0.013335214321633237f,
    0.01f, 0.007498942093324559f, 0.005623413251903491f, 0.004216965034285823f,
    0.0031622776601683794f, 0.002371373705661655f, 0.001778279410038923f, 0.0013335214321633237f,
    0.001f, 0.0007498942093324559f, 0.0005623413251903491f, 0.0004216965034285823f,
    0.00031622776601683794f, 0.0002371373705661655f, 0.0001778279410038923f, 0.00013335214321633237f
};

// ============================ fp32 -> bf16 hi/lo split ============================
__global__ __launch_bounds__(256) void split_bf16(const float* __restrict__ src,
                                                  __nv_bfloat16* __restrict__ hi,
                                                  __nv_bfloat16* __restrict__ lo,
                                                  int n4)
{
    int i = blockIdx.x * 256 + threadIdx.x;
    if (i >= n4) return;
    float4 v = ((const float4*)src)[i];
    float f[4] = {v.x, v.y, v.z, v.w};
    __nv_bfloat16 h[4], l[4];
#pragma unroll
    for (int j = 0; j < 4; j++) {
        h[j] = __float2bfloat16(f[j]);
        l[j] = __float2bfloat16(f[j] - __bfloat162float(h[j]));
    }
    ((__nv_bfloat162*)hi)[2 * i + 0] = __nv_bfloat162(h[0], h[1]);
    ((__nv_bfloat162*)hi)[2 * i + 1] = __nv_bfloat162(h[2], h[3]);
    ((__nv_bfloat162*)lo)[2 * i + 0] = __nv_bfloat162(l[0], l[1]);
    ((__nv_bfloat162*)lo)[2 * i + 1] = __nv_bfloat162(l[2], l[3]);
}

// ============================ HMMA bf16x3 GEMM ============================
// C[4096,1024] = A * W^T, fp32 via bf16 hi/lo 3-product split on mma.sync.
// 128x128 tile, 8 warps (2m x 4n), warp tile 64x32, K-chunk 64, double buffer.
// smem per stage: Ahi(16K) Alo(16K) Bhi(16K) Blo(16K) = 64KB; 2 stages = 128KB.
#define GT_STAGE 65536
#define GT_SMEM_TOTAL (2 * GT_STAGE)
#define NCHUNK 16

__device__ __forceinline__ void gt_fill(uint32_t sb, int stage,
                                        const __nv_bfloat16* Ahi, const __nv_bfloat16* Alo,
                                        const __nv_bfloat16* Bhi, const __nv_bfloat16* Blo,
                                        int m0, int n0, int k0, int tid)
{
    uint32_t base = sb + stage * GT_STAGE;
#pragma unroll
    for (int j = 0; j < 4; j++) {
        int id  = tid + j * 256;      // 0..1023
        int r   = id >> 3;            // row 0..127
        int c16 = id & 7;             // 16B chunk within 128B row
        uint32_t sw = SMEM_SWIZZLE_128B((uint32_t)(r * 128 + c16 * 16));
        size_t aoff = (size_t)(m0 + r) * D_ + k0 + c16 * 8;
        size_t boff = (size_t)(n0 + r) * D_ + k0 + c16 * 8;
        cp_async16(base + 0     + sw, Ahi + aoff);
        cp_async16(base + 16384 + sw, Alo + aoff);
        cp_async16(base + 32768 + sw, Bhi + boff);
        cp_async16(base + 49152 + sw, Blo + boff);
    }
}

__device__ void gemm_mma_body(const __nv_bfloat16* __restrict__ Ahi,
                              const __nv_bfloat16* __restrict__ Alo,
                              const __nv_bfloat16* __restrict__ Bhi,
                              const __nv_bfloat16* __restrict__ Blo,
                              float* __restrict__ C)
{
    extern __shared__ __align__(1024) char smem[];
    uint32_t sb = smem_u32(smem);
    const int tid = threadIdx.x;
    const int wid = tid >> 5;
    const int lid = tid & 31;
    const int wm  = wid >> 2;        // 0..1  (m 64)
    const int wn  = wid & 3;         // 0..3  (n 32)
    const int m0  = blockIdx.y * 128;
    const int n0  = blockIdx.x * 128;

    float acc[4][4][4];
#pragma unroll
    for (int mt = 0; mt < 4; mt++)
#pragma unroll
        for (int nt = 0; nt < 4; nt++)
#pragma unroll
            for (int r = 0; r < 4; r++) acc[mt][nt][r] = 0.0f;

    gt_fill(sb, 0, Ahi, Alo, Bhi, Blo, m0, n0, 0, tid);
    CP_COMMIT();
    gt_fill(sb, 1, Ahi, Alo, Bhi, Blo, m0, n0, 64, tid);
    CP_COMMIT();

    // precomputed ldmatrix lane geometry
    const int a_row = (lid & 15);                       // within m16 tile
    const int a_kc  = (lid >> 4);                       // 0/1: k 16B chunk
    const int b_row = (lid & 7) + ((lid >> 4) << 3);    // within n16 group
    const int b_kc  = (lid >> 3) & 1;

    for (int i = 0; i < NCHUNK; i++) {
        if (i == NCHUNK - 1) asm volatile("cp.async.wait_group 0;" ::: "memory");
        else                 asm volatile("cp.async.wait_group 1;" ::: "memory");
        __syncthreads();

        const uint32_t tb = sb + (i & 1) * GT_STAGE;

#pragma unroll
        for (int ks = 0; ks < 4; ks++) {
            // ---- B fragments: 2 x (n16) groups, hi + lo ----
            uint32_t bhi[4][2], blo[4][2];
#pragma unroll
            for (int ng = 0; ng < 2; ng++) {
                const int nrow = wn * 32 + ng * 16 + b_row;
                const uint32_t off = (uint32_t)(nrow * 128 + (ks * 2 + b_kc) * 16);
                const uint32_t sw = SMEM_SWIZZLE_128B(off);
                uint32_t r[4];
                ldm_x4(r, tb + 32768 + sw);
                bhi[2 * ng][0] = r[0]; bhi[2 * ng][1] = r[1];
                bhi[2 * ng + 1][0] = r[2]; bhi[2 * ng + 1][1] = r[3];
                ldm_x4(r, tb + 49152 + sw);
                blo[2 * ng][0] = r[0]; blo[2 * ng][1] = r[1];
                blo[2 * ng + 1][0] = r[2]; blo[2 * ng + 1][1] = r[3];
            }
            // ---- A fragments per m16 tile; 3-product MMA ----
#pragma unroll
            for (int mt = 0; mt < 4; mt++) {
                const int mrow = wm * 64 + mt * 16 + a_row;
                const uint32_t off = (uint32_t)(mrow * 128 + (ks * 2 + a_kc) * 16);
                const uint32_t sw = SMEM_SWIZZLE_128B(off);
                uint32_t ahi[4], alo[4];
                ldm_x4(ahi, tb + 0 + sw);
                ldm_x4(alo, tb + 16384 + sw);
#pragma unroll
                for (int nt = 0; nt < 4; nt++) {
                    mma16816(acc[mt][nt], ahi, bhi[nt]);
                    mma16816(acc[mt][nt], ahi, blo[nt]);
                    mma16816(acc[mt][nt], alo, bhi[nt]);
                }
            }
        }
        __syncthreads();

        if (i + 2 < NCHUNK) {
            gt_fill(sb, i & 1, Ahi, Alo, Bhi, Blo, m0, n0, (i + 2) * 64, tid);
            CP_COMMIT();
        }
    }

    // ---- epilogue ----
    const int g  = lid >> 2;
    const int t4 = lid & 3;
#pragma unroll
    for (int mt = 0; mt < 4; mt++) {
        const int row = m0 + wm * 64 + mt * 16 + g;
#pragma unroll
        for (int nt = 0; nt < 4; nt++) {
            const int col = n0 + wn * 32 + nt * 8 + t4 * 2;
            *(float2*)&C[(size_t)row * D_ + col]       = make_float2(acc[mt][nt][0], acc[mt][nt][1]);
            *(float2*)&C[(size_t)(row + 8) * D_ + col] = make_float2(acc[mt][nt][2], acc[mt][nt][3]);
        }
    }
}

__global__ __launch_bounds__(256) void gemm_mma_qkv(const __nv_bfloat16* __restrict__ xhi,
                                                    const __nv_bfloat16* __restrict__ xlo,
                                                    const __nv_bfloat16* __restrict__ whi,
                                                    const __nv_bfloat16* __restrict__ wlo,
                                                    float* __restrict__ q,
                                                    float* __restrict__ k,
                                                    float* __restrict__ v)
{
    const int z = blockIdx.z;
    float* C = (z == 0) ? q : (z == 1) ? k : v;
    gemm_mma_body(xhi, xlo, whi + (size_t)z * D_ * D_, wlo + (size_t)z * D_ * D_, C);
}

__global__ __launch_bounds__(256) void gemm_mma_one(const __nv_bfloat16* __restrict__ ahi,
                                                    const __nv_bfloat16* __restrict__ alo,
                                                    const __nv_bfloat16* __restrict__ whi,
                                                    const __nv_bfloat16* __restrict__ wlo,
                                                    float* __restrict__ C)
{
    gemm_mma_body(ahi, alo, whi, wlo, C);
}

// ============================ RoPE ============================
__global__ __launch_bounds__(256) void rope_kernel(float* __restrict__ q,
                                                   float* __restrict__ k,
                                                   const int* __restrict__ pos)
{
    const int t = blockIdx.x * 256 + threadIdx.x;
    if (t >= BL_ * (D_ / 2)) return;

    const int bl = t >> 9;
    const int e2 = t & 511;
    const int p  = e2 & 31;
    const int l  = bl & (L_ - 1);

    const float ang = (float)pos[l] * g_invfreq[p];
    float s, c;
    sincosf(ang, &s, &c);

    float2* q2 = (float2*)q;
    float2* k2 = (float2*)k;

    float2 v = q2[t];
    q2[t] = make_float2(v.x * c - v.y * s, v.x * s + v.y * c);
    v = k2[t];
    k2[t] = make_float2(v.x * c - v.y * s, v.x * s + v.y * c);
}

// ============================ flash attention (f32x2) ============================
__global__ __launch_bounds__(256) void attn_kernel(const float* __restrict__ Q,
                                                   const float* __restrict__ Kp,
                                                   const float* __restrict__ Vp,
                                                   float* __restrict__ O)
{
    __shared__ float Qs[64 * 64];
    __shared__ float KPs[64 * 64];
    __shared__ float Vs[64 * 64];

    const int tid = threadIdx.x;
    const int tx  = tid & 15;
    const int ty  = tid >> 4;
    const int qt  = blockIdx.x;
    const int h   = blockIdx.y;
    const int b   = blockIdx.z;
    const int q0  = qt * 64;

    const int lrow = tid >> 2;
    const int lc16 = (tid & 3) * 16;

    {
        const float* src = Q + (size_t)(b * L_ + q0 + lrow) * D_ + h * DH_ + lc16;
#pragma unroll
        for (int c = 0; c < 16; c += 4) {
            float4 v = *(const float4*)(src + c);
            Qs[(lc16 + c + 0) * 64 + lrow] = v.x;
            Qs[(lc16 + c + 1) * 64 + lrow] = v.y;
            Qs[(lc16 + c + 2) * 64 + lrow] = v.z;
            Qs[(lc16 + c + 3) * 64 + lrow] = v.w;
        }
    }

    float m_run[4], l_run[4];
    ull acc2[4][2];
#pragma unroll
    for (int i = 0; i < 4; i++) {
        m_run[i] = -1e30f;
        l_run[i] = 0.0f;
        acc2[i][0] = 0ull;
        acc2[i][1] = 0ull;
    }

    for (int kt = 0; kt <= qt; kt++) {
        const int k0 = kt * 64;

        __syncthreads();

        {
            const float* ks = Kp + (size_t)(b * L_ + k0 + lrow) * D_ + h * DH_ + lc16;
            const float* vs = Vp + (size_t)(b * L_ + k0 + lrow) * D_ + h * DH_ + lc16;
#pragma unroll
            for (int c = 0; c < 16; c += 4) {
                float4 kv = *(const float4*)(ks + c);
                KPs[(lc16 + c + 0) * 64 + lrow] = kv.x;
                KPs[(lc16 + c + 1) * 64 + lrow] = kv.y;
                KPs[(lc16 + c + 2) * 64 + lrow] = kv.z;
                KPs[(lc16 + c + 3) * 64 + lrow] = kv.w;
                float4 vv = *(const float4*)(vs + c);
                *(float4*)&Vs[lrow * 64 + lc16 + c] = vv;
            }
        }
        __syncthreads();

        ull s2[4][2];
#pragma unroll
        for (int i = 0; i < 4; i++) { s2[i][0] = 0ull; s2[i][1] = 0ull; }

#pragma unroll 8
        for (int kk = 0; kk < 64; kk++) {
            float4 q4 = *(const float4*)&Qs[kk * 64 + ty * 4];
            float4 k4 = *(const float4*)&KPs[kk * 64 + tx * 4];
            ull k01 = pk2(k4.x, k4.y);
            ull k23 = pk2(k4.z, k4.w);
            float qv[4] = {q4.x, q4.y, q4.z, q4.w};
#pragma unroll
            for (int i = 0; i < 4; i++) {
                ull qi = pk2(qv[i], qv[i]);
                s2[i][0] = fma2_(qi, k01, s2[i][0]);
                s2[i][1] = fma2_(qi, k23, s2[i][1]);
            }
        }

        float s[4][4];
        const bool diag = (kt == qt);
#pragma unroll
        for (int i = 0; i < 4; i++) {
            upk2(s2[i][0], s[i][0], s[i][1]);
            upk2(s2[i][1], s[i][2], s[i][3]);
#pragma unroll
            for (int j = 0; j < 4; j++) {
                float v = s[i][j] * 0.125f;
                if (diag && (tx * 4 + j > ty * 4 + i)) v = -1e30f;
                s[i][j] = v;
            }
        }

        float mnew[4], corr[4];
#pragma unroll
        for (int i = 0; i < 4; i++) {
            float mx = fmaxf(fmaxf(s[i][0], s[i][1]), fmaxf(s[i][2], s[i][3]));
#pragma unroll
            for (int o = 8; o > 0; o >>= 1)
                mx = fmaxf(mx, __shfl_xor_sync(0xffffffffu, mx, o, 16));
            mnew[i] = fmaxf(m_run[i], mx);
            corr[i] = __expf(m_run[i] - mnew[i]);
        }

        __syncthreads();

#pragma unroll
        for (int i = 0; i < 4; i++) {
            float ps = 0.0f;
#pragma unroll
            for (int j = 0; j < 4; j++) {
                float p = __expf(s[i][j] - mnew[i]);
                s[i][j] = p;
                ps += p;
            }
#pragma unroll
            for (int o = 8; o > 0; o >>= 1)
                ps += __shfl_xor_sync(0xffffffffu, ps, o, 16);
            l_run[i] = l_run[i] * corr[i] + ps;
            m_run[i] = mnew[i];
            ull cp = pk2(corr[i], corr[i]);
            acc2[i][0] = mul2_(cp, acc2[i][0]);
            acc2[i][1] = mul2_(cp, acc2[i][1]);
            *(float4*)&KPs[(ty * 4 + i) * 64 + tx * 4] = *(float4*)&s[i][0];
        }
        __syncthreads();

#pragma unroll 4
        for (int kk0 = 0; kk0 < 64; kk0 += 4) {
            float4 p4[4];
#pragma unroll
            for (int i = 0; i < 4; i++)
                p4[i] = *(const float4*)&KPs[(ty * 4 + i) * 64 + kk0];
#pragma unroll
            for (int kx = 0; kx < 4; kx++) {
                float4 v4 = *(const float4*)&Vs[(kk0 + kx) * 64 + tx * 4];
                ull v01 = pk2(v4.x, v4.y);
                ull v23 = pk2(v4.z, v4.w);
#pragma unroll
                for (int i = 0; i < 4; i++) {
                    float p = (kx == 0) ? p4[i].x : (kx == 1) ? p4[i].y
                            : (kx == 2) ? p4[i].z : p4[i].w;
                    ull pp = pk2(p, p);
                    acc2[i][0] = fma2_(pp, v01, acc2[i][0]);
                    acc2[i][1] = fma2_(pp, v23, acc2[i][1]);
                }
            }
        }
    }

    float* op = O + (size_t)(b * L_ + q0) * D_ + h * DH_;
#pragma unroll
    for (int i = 0; i < 4; i++) {
        float inv = 1.0f / l_run[i];
        float o4[4];
        upk2(acc2[i][0], o4[0], o4[1]);
        upk2(acc2[i][1], o4[2], o4[3]);
#pragma unroll
        for (int j = 0; j < 4; j++) o4[j] *= inv;
        *(float4*)(op + (ty * 4 + i) * D_ + tx * 4) = *(float4*)o4;
    }
}

// ============================ launch ============================
extern "C" void kernel_launch(void* const* d_in, const int* in_sizes, int n_in,
                              void* d_out, int out_size)
{
    const float* x   = (const float*)d_in[0];
    const float* Wq  = (const float*)d_in[1];
    const float* Wk  = (const float*)d_in[2];
    const float* Wv  = (const float*)d_in[3];
    const float* Wo  = (const float*)d_in[4];
    const int*   pos = (const int*)  d_in[5];
    float* out = (float*)d_out;

    float *q_ptr, *k_ptr, *v_ptr, *o_ptr;
    cudaGetSymbolAddress((void**)&q_ptr, g_q);
    cudaGetSymbolAddress((void**)&k_ptr, g_k);
    cudaGetSymbolAddress((void**)&v_ptr, g_v);
    cudaGetSymbolAddress((void**)&o_ptr, g_o);
    __nv_bfloat16 *xhi, *xlo, *ohi, *olo, *whi, *wlo;
    cudaGetSymbolAddress((void**)&xhi, g_xhi);
    cudaGetSymbolAddress((void**)&xlo, g_xlo);
    cudaGetSymbolAddress((void**)&ohi, g_ohi);
    cudaGetSymbolAddress((void**)&olo, g_olo);
    cudaGetSymbolAddress((void**)&whi, g_whi);
    cudaGetSymbolAddress((void**)&wlo, g_wlo);

    cudaFuncSetAttribute(gemm_mma_qkv, cudaFuncAttributeMaxDynamicSharedMemorySize, GT_SMEM_TOTAL);
    cudaFuncSetAttribute(gemm_mma_one, cudaFuncAttributeMaxDynamicSharedMemorySize, GT_SMEM_TOTAL);

    const int nx4 = BL_ * D_ / 4;     // 1048576
    const int nw4 = D_ * D_ / 4;      // 262144

    split_bf16<<<nx4 / 256, 256>>>(x, xhi, xlo, nx4);
    split_bf16<<<nw4 / 256, 256>>>(Wq, whi + 0 * (size_t)D_ * D_, wlo + 0 * (size_t)D_ * D_, nw4);
    split_bf16<<<nw4 / 256, 256>>>(Wk, whi + 1 * (size_t)D_ * D_, wlo + 1 * (size_t)D_ * D_, nw4);
    split_bf16<<<nw4 / 256, 256>>>(Wv, whi + 2 * (size_t)D_ * D_, wlo + 2 * (size_t)D_ * D_, nw4);
    split_bf16<<<nw4 / 256, 256>>>(Wo, whi + 3 * (size_t)D_ * D_, wlo + 3 * (size_t)D_ * D_, nw4);

    dim3 qkv_grid(D_ / 128, BL_ / 128, 3);   // (8, 32, 3)
    gemm_mma_qkv<<<qkv_grid, 256, GT_SMEM_TOTAL>>>(xhi, xlo, whi, wlo, q_ptr, k_ptr, v_ptr);

    rope_kernel<<<(BL_ * (D_ / 2)) / 256, 256>>>(q_ptr, k_ptr, pos);

    attn_kernel<<<dim3(L_ / 64, H_, B_), 256>>>(q_ptr, k_ptr, v_ptr, o_ptr);

    split_bf16<<<nx4 / 256, 256>>>(o_ptr, ohi, olo, nx4);

    dim3 ggrid(D_ / 128, BL_ / 128);
    gemm_mma_one<<<ggrid, 256, GT_SMEM_TOTAL>>>(ohi, olo,
                                                whi + 3 * (size_t)D_ * D_,
                                                wlo + 3 * (size_t)D_ * D_, out);
}

// round 5
// speedup vs baseline: 3.0352x; 1.8644x over previous
#include <cuda_runtime.h>
#include <cuda_bf16.h>
#include <cstdint>

#define B_  2
#define L_  2048
#define D_  1024
#define H_  16
#define DH_ 64
#define BL_ (B_ * L_)

// ============================ helpers ============================
__device__ __forceinline__ uint32_t smem_u32(const void* p) {
    uint32_t a;
    asm("{ .reg .u64 t; cvta.to.shared.u64 t, %1; cvt.u32.u64 %0, t; }" : "=r"(a) : "l"(p));
    return a;
}
#define SMEM_SWIZZLE_128B(x) ((x) ^ (((x) >> 3) & 0x70))

__device__ __forceinline__ void cp_async16(uint32_t dst, const void* src) {
    asm volatile("cp.async.ca.shared.global [%0], [%1], 16;" :: "r"(dst), "l"(src) : "memory");
}
#define CP_COMMIT() asm volatile("cp.async.commit_group;" ::: "memory")

__device__ __forceinline__ void ldm_x4(uint32_t* r, uint32_t addr) {
    asm volatile("ldmatrix.sync.aligned.m8n8.x4.shared.b16 {%0,%1,%2,%3}, [%4];"
        : "=r"(r[0]), "=r"(r[1]), "=r"(r[2]), "=r"(r[3]) : "r"(addr));
}
__device__ __forceinline__ void ldm_x4_t(uint32_t* r, uint32_t addr) {
    asm volatile("ldmatrix.sync.aligned.m8n8.x4.trans.shared.b16 {%0,%1,%2,%3}, [%4];"
        : "=r"(r[0]), "=r"(r[1]), "=r"(r[2]), "=r"(r[3]) : "r"(addr));
}

// D = A*B + D  (m16n8k16, bf16 in, fp32 accum)
__device__ __forceinline__ void mma16816(float* c, const uint32_t* a, const uint32_t* b) {
    asm volatile("mma.sync.aligned.m16n8k16.row.col.f32.bf16.bf16.f32 "
        "{%0,%1,%2,%3}, {%4,%5,%6,%7}, {%8,%9}, {%0,%1,%2,%3};"
        : "+f"(c[0]), "+f"(c[1]), "+f"(c[2]), "+f"(c[3])
        : "r"(a[0]), "r"(a[1]), "r"(a[2]), "r"(a[3]), "r"(b[0]), "r"(b[1]));
}

// exp(x) for x <= 0, on FMA/ALU pipes (no MUFU). abs err <= ~3e-5.
__device__ __forceinline__ float exp_fast(float x) {
    float t = x * 1.44269504f;
    t = fmaxf(t, -126.0f);
    float fi = floorf(t);
    float f = t - fi;
    float r = 1.54035304e-4f;
    r = fmaf(r, f, 1.33335581e-3f);
    r = fmaf(r, f, 9.61812911e-3f);
    r = fmaf(r, f, 5.55041087e-2f);
    r = fmaf(r, f, 2.40226507e-1f);
    r = fmaf(r, f, 6.93147181e-1f);
    r = fmaf(r, f, 1.0f);
    return r * __int_as_float(((int)fi + 127) << 23);
}

// pack two floats into bf16x2 hi and bf16x2 lo (residual) words
__device__ __forceinline__ void hilo_pack(float a, float b, uint32_t& hi, uint32_t& lo) {
    __nv_bfloat16 ah = __float2bfloat16(a);
    __nv_bfloat16 bh = __float2bfloat16(b);
    __nv_bfloat16 al = __float2bfloat16(a - __bfloat162float(ah));
    __nv_bfloat16 bl = __float2bfloat16(b - __bfloat162float(bh));
    __nv_bfloat162 h2(ah, bh), l2(al, bl);
    hi = *(uint32_t*)&h2;
    lo = *(uint32_t*)&l2;
}

// ============================ scratch globals ============================
__device__ float g_q[BL_ * D_];
__device__ float g_k[BL_ * D_];
__device__ float g_v[BL_ * D_];
__device__ __nv_bfloat16 g_xhi[BL_ * D_];
__device__ __nv_bfloat16 g_xlo[BL_ * D_];
__device__ __nv_bfloat16 g_whi[4 * D_ * D_];
__device__ __nv_bfloat16 g_wlo[4 * D_ * D_];
__device__ __nv_bfloat16 g_qhi[BL_ * D_];
__device__ __nv_bfloat16 g_qlo[BL_ * D_];
__device__ __nv_bfloat16 g_khi[BL_ * D_];
__device__ __nv_bfloat16 g_klo[BL_ * D_];
__device__ __nv_bfloat16 g_vhi[BL_ * D_];
__device__ __nv_bfloat16 g_vlo[BL_ * D_];
__device__ __nv_bfloat16 g_ohi[BL_ * D_];
__device__ __nv_bfloat16 g_olo[BL_ * D_];

__device__ const float g_invfreq[32] = {
    1.0f, 0.7498942093324559f, 0.5623413251903491f, 0.4216965034285823f,
    0.31622776601683794f, 0.2371373705661655f, 0.1778279410038923f, 0.13335214321633237f,
    0.1f, 0.07498942093324559f, 0.05623413251903491f, 0.04216965034285823f,
    0.031622776601683794f, 0.02371373705661655f, 0.01778279410038923f, 0.013335214321633237f,
    0.01f, 0.007498942093324559f, 0.005623413251903491f, 0.004216965034285823f,
    0.0031622776601683794f, 0.002371373705661655f, 0.001778279410038923f, 0.0013335214321633237f,
    0.001f, 0.0007498942093324559f, 0.0005623413251903491f, 0.0004216965034285823f,
    0.00031622776601683794f, 0.0002371373705661655f, 0.0001778279410038923f, 0.00013335214321633237f
};

// ============================ fp32 -> bf16 hi/lo split ============================
__global__ __launch_bounds__(256) void split_bf16(const float* __restrict__ src,
                                                  __nv_bfloat16* __restrict__ hi,
                                                  __nv_bfloat16* __restrict__ lo,
                                                  int n4)
{
    int i = blockIdx.x * 256 + threadIdx.x;
    if (i >= n4) return;
    float4 v = ((const float4*)src)[i];
    float f[4] = {v.x, v.y, v.z, v.w};
    __nv_bfloat16 h[4], l[4];
#pragma unroll
    for (int j = 0; j < 4; j++) {
        h[j] = __float2bfloat16(f[j]);
        l[j] = __float2bfloat16(f[j] - __bfloat162float(h[j]));
    }
    ((__nv_bfloat162*)hi)[2 * i + 0] = __nv_bfloat162(h[0], h[1]);
    ((__nv_bfloat162*)hi)[2 * i + 1] = __nv_bfloat162(h[2], h[3]);
    ((__nv_bfloat162*)lo)[2 * i + 0] = __nv_bfloat162(l[0], l[1]);
    ((__nv_bfloat162*)lo)[2 * i + 1] = __nv_bfloat162(l[2], l[3]);
}

// ============================ HMMA bf16x3 GEMM (validated R4) ============================
#define GT_STAGE 65536
#define GT_SMEM_TOTAL (2 * GT_STAGE)
#define NCHUNK 16

__device__ __forceinline__ void gt_fill(uint32_t sb, int stage,
                                        const __nv_bfloat16* Ahi, const __nv_bfloat16* Alo,
                                        const __nv_bfloat16* Bhi, const __nv_bfloat16* Blo,
                                        int m0, int n0, int k0, int tid)
{
    uint32_t base = sb + stage * GT_STAGE;
#pragma unroll
    for (int j = 0; j < 4; j++) {
        int id  = tid + j * 256;
        int r   = id >> 3;
        int c16 = id & 7;
        uint32_t sw = SMEM_SWIZZLE_128B((uint32_t)(r * 128 + c16 * 16));
        size_t aoff = (size_t)(m0 + r) * D_ + k0 + c16 * 8;
        size_t boff = (size_t)(n0 + r) * D_ + k0 + c16 * 8;
        cp_async16(base + 0     + sw, Ahi + aoff);
        cp_async16(base + 16384 + sw, Alo + aoff);
        cp_async16(base + 32768 + sw, Bhi + boff);
        cp_async16(base + 49152 + sw, Blo + boff);
    }
}

__device__ void gemm_mma_body(const __nv_bfloat16* __restrict__ Ahi,
                              const __nv_bfloat16* __restrict__ Alo,
                              const __nv_bfloat16* __restrict__ Bhi,
                              const __nv_bfloat16* __restrict__ Blo,
                              float* __restrict__ C)
{
    extern __shared__ __align__(1024) char smem[];
    uint32_t sb = smem_u32(smem);
    const int tid = threadIdx.x;
    const int wid = tid >> 5;
    const int lid = tid & 31;
    const int wm  = wid >> 2;
    const int wn  = wid & 3;
    const int m0  = blockIdx.y * 128;
    const int n0  = blockIdx.x * 128;

    float acc[4][4][4];
#pragma unroll
    for (int mt = 0; mt < 4; mt++)
#pragma unroll
        for (int nt = 0; nt < 4; nt++)
#pragma unroll
            for (int r = 0; r < 4; r++) acc[mt][nt][r] = 0.0f;

    gt_fill(sb, 0, Ahi, Alo, Bhi, Blo, m0, n0, 0, tid);
    CP_COMMIT();
    gt_fill(sb, 1, Ahi, Alo, Bhi, Blo, m0, n0, 64, tid);
    CP_COMMIT();

    const int a_row = (lid & 15);
    const int a_kc  = (lid >> 4);
    const int b_row = (lid & 7) + ((lid >> 4) << 3);
    const int b_kc  = (lid >> 3) & 1;

    for (int i = 0; i < NCHUNK; i++) {
        if (i == NCHUNK - 1) asm volatile("cp.async.wait_group 0;" ::: "memory");
        else                 asm volatile("cp.async.wait_group 1;" ::: "memory");
        __syncthreads();

        const uint32_t tb = sb + (i & 1) * GT_STAGE;

#pragma unroll
        for (int ks = 0; ks < 4; ks++) {
            uint32_t bhi[4][2], blo[4][2];
#pragma unroll
            for (int ng = 0; ng < 2; ng++) {
                const int nrow = wn * 32 + ng * 16 + b_row;
                const uint32_t off = (uint32_t)(nrow * 128 + (ks * 2 + b_kc) * 16);
                const uint32_t sw = SMEM_SWIZZLE_128B(off);
                uint32_t r[4];
                ldm_x4(r, tb + 32768 + sw);
                bhi[2 * ng][0] = r[0]; bhi[2 * ng][1] = r[1];
                bhi[2 * ng + 1][0] = r[2]; bhi[2 * ng + 1][1] = r[3];
                ldm_x4(r, tb + 49152 + sw);
                blo[2 * ng][0] = r[0]; blo[2 * ng][1] = r[1];
                blo[2 * ng + 1][0] = r[2]; blo[2 * ng + 1][1] = r[3];
            }
#pragma unroll
            for (int mt = 0; mt < 4; mt++) {
                const int mrow = wm * 64 + mt * 16 + a_row;
                const uint32_t off = (uint32_t)(mrow * 128 + (ks * 2 + a_kc) * 16);
                const uint32_t sw = SMEM_SWIZZLE_128B(off);
                uint32_t ahi[4], alo[4];
                ldm_x4(ahi, tb + 0 + sw);
                ldm_x4(alo, tb + 16384 + sw);
#pragma unroll
                for (int nt = 0; nt < 4; nt++) {
                    mma16816(acc[mt][nt], ahi, bhi[nt]);
                    mma16816(acc[mt][nt], ahi, blo[nt]);
                    mma16816(acc[mt][nt], alo, bhi[nt]);
                }
            }
        }
        __syncthreads();

        if (i + 2 < NCHUNK) {
            gt_fill(sb, i & 1, Ahi, Alo, Bhi, Blo, m0, n0, (i + 2) * 64, tid);
            CP_COMMIT();
        }
    }

    const int g  = lid >> 2;
    const int t4 = lid & 3;
#pragma unroll
    for (int mt = 0; mt < 4; mt++) {
        const int row = m0 + wm * 64 + mt * 16 + g;
#pragma unroll
        for (int nt = 0; nt < 4; nt++) {
            const int col = n0 + wn * 32 + nt * 8 + t4 * 2;
            *(float2*)&C[(size_t)row * D_ + col]       = make_float2(acc[mt][nt][0], acc[mt][nt][1]);
            *(float2*)&C[(size_t)(row + 8) * D_ + col] = make_float2(acc[mt][nt][2], acc[mt][nt][3]);
        }
    }
}

__global__ __launch_bounds__(256) void gemm_mma_qkv(const __nv_bfloat16* __restrict__ xhi,
                                                    const __nv_bfloat16* __restrict__ xlo,
                                                    const __nv_bfloat16* __restrict__ whi,
                                                    const __nv_bfloat16* __restrict__ wlo,
                                                    float* __restrict__ q,
                                                    float* __restrict__ k,
                                                    float* __restrict__ v)
{
    const int z = blockIdx.z;
    float* C = (z == 0) ? q : (z == 1) ? k : v;
    gemm_mma_body(xhi, xlo, whi + (size_t)z * D_ * D_, wlo + (size_t)z * D_ * D_, C);
}

__global__ __launch_bounds__(256) void gemm_mma_one(const __nv_bfloat16* __restrict__ ahi,
                                                    const __nv_bfloat16* __restrict__ alo,
                                                    const __nv_bfloat16* __restrict__ whi,
                                                    const __nv_bfloat16* __restrict__ wlo,
                                                    float* __restrict__ C)
{
    gemm_mma_body(ahi, alo, whi, wlo, C);
}

// ============================ RoPE + split to bf16 hi/lo ============================
// Q is pre-scaled by 1/sqrt(Dh) = 0.125 (exact power of 2, hi/lo split unaffected).
__global__ __launch_bounds__(256) void rope_split(const float* __restrict__ q,
                                                  const float* __restrict__ k,
                                                  const int* __restrict__ pos,
                                                  __nv_bfloat16* __restrict__ qhi,
                                                  __nv_bfloat16* __restrict__ qlo,
                                                  __nv_bfloat16* __restrict__ khi,
                                                  __nv_bfloat16* __restrict__ klo)
{
    const int t = blockIdx.x * 256 + threadIdx.x;
    if (t >= BL_ * (D_ / 2)) return;

    const int e2 = t & 511;
    const int p  = e2 & 31;
    const int l  = (t >> 9) & (L_ - 1);

    const float ang = (float)pos[l] * g_invfreq[p];
    float s, c;
    sincosf(ang, &s, &c);

    float2 v = ((const float2*)q)[t];
    float a0 = (v.x * c - v.y * s) * 0.125f;
    float a1 = (v.x * s + v.y * c) * 0.125f;
    uint32_t hi, lo;
    hilo_pack(a0, a1, hi, lo);
    ((uint32_t*)qhi)[t] = hi;
    ((uint32_t*)qlo)[t] = lo;

    v = ((const float2*)k)[t];
    a0 = v.x * c - v.y * s;
    a1 = v.x * s + v.y * c;
    hilo_pack(a0, a1, hi, lo);
    ((uint32_t*)khi)[t] = hi;
    ((uint32_t*)klo)[t] = lo;
}

// ============================ tensor-core flash attention ============================
// CTA: 64 q-rows x (all K tiles of 64), 4 warps, warp = 16 q-rows.
// smem: Qhi[8K] Qlo[8K] | stage{0,1}: Khi Klo Vhi Vlo (8K each).
#define AT_KV0  16384
#define AT_STAGE 32768
#define AT_SMEM (16384 + 2 * 32768)

__device__ __forceinline__ void at_fill(uint32_t sb, int stage, size_t gbase, int k0,
                                        const __nv_bfloat16* khi, const __nv_bfloat16* klo,
                                        const __nv_bfloat16* vhi, const __nv_bfloat16* vlo,
                                        int tid)
{
    uint32_t kb = sb + AT_KV0 + stage * AT_STAGE;
#pragma unroll
    for (int j = 0; j < 4; j++) {
        int id = tid + j * 128;         // 0..511
        int r  = id >> 3;
        int c  = id & 7;
        uint32_t sw = SMEM_SWIZZLE_128B((uint32_t)(r * 128 + c * 16));
        size_t off = gbase + (size_t)(k0 + r) * D_ + c * 8;
        cp_async16(kb + 0     + sw, khi + off);
        cp_async16(kb + 8192  + sw, klo + off);
        cp_async16(kb + 16384 + sw, vhi + off);
        cp_async16(kb + 24576 + sw, vlo + off);
    }
}

__global__ __launch_bounds__(128) void attn_mma(const __nv_bfloat16* __restrict__ qhi,
                                                const __nv_bfloat16* __restrict__ qlo,
                                                const __nv_bfloat16* __restrict__ khi,
                                                const __nv_bfloat16* __restrict__ klo,
                                                const __nv_bfloat16* __restrict__ vhi,
                                                const __nv_bfloat16* __restrict__ vlo,
                                                __nv_bfloat16* __restrict__ ohi,
                                                __nv_bfloat16* __restrict__ olo)
{
    extern __shared__ __align__(1024) char smem[];
    uint32_t sb = smem_u32(smem);
    const int tid = threadIdx.x;
    const int wid = tid >> 5;
    const int lid = tid & 31;
    const int qt  = (L_ / 64 - 1) - blockIdx.x;   // big tiles scheduled first
    const int h   = blockIdx.y;
    const int b   = blockIdx.z;
    const int q0  = qt * 64;
    const size_t gbase = (size_t)(b * L_) * D_ + h * DH_;

    // ---- load Q tiles (hi, lo) ----
#pragma unroll
    for (int j = 0; j < 4; j++) {
        int id = tid + j * 128;
        int r  = id >> 3;
        int c  = id & 7;
        uint32_t sw = SMEM_SWIZZLE_128B((uint32_t)(r * 128 + c * 16));
        size_t off = gbase + (size_t)(q0 + r) * D_ + c * 8;
        cp_async16(sb + 0    + sw, qhi + off);
        cp_async16(sb + 8192 + sw, qlo + off);
    }
    CP_COMMIT();
    at_fill(sb, 0, gbase, 0, khi, klo, vhi, vlo, tid);
    CP_COMMIT();
    asm volatile("cp.async.wait_group 0;" ::: "memory");
    __syncthreads();

    // ---- Q fragments (A layout, validated in R4 GEMM) ----
    uint32_t qh[4][4], ql[4][4];
    {
        const int arow = wid * 16 + (lid & 15);
        const int akc  = lid >> 4;
#pragma unroll
        for (int ks = 0; ks < 4; ks++) {
            uint32_t sw = SMEM_SWIZZLE_128B((uint32_t)(arow * 128 + (ks * 2 + akc) * 16));
            ldm_x4(qh[ks], sb + 0 + sw);
            ldm_x4(ql[ks], sb + 8192 + sw);
        }
    }

    float m_run[2] = {-1e30f, -1e30f};
    float l_run[2] = {0.0f, 0.0f};
    float o[8][4];
#pragma unroll
    for (int j = 0; j < 8; j++)
#pragma unroll
        for (int r = 0; r < 4; r++) o[j][r] = 0.0f;

    const int brow = (lid & 7) + ((lid >> 4) << 3);
    const int bkc  = (lid >> 3) & 1;
    const int vrow = lid & 15;
    const int vcol = (lid >> 4) << 3;
    const int nkt  = qt + 1;

    for (int kt = 0; kt < nkt; kt++) {
        __syncthreads();    // all warps done reading stage (kt+1)&1 from iter kt-1
        if (kt + 1 < nkt) {
            at_fill(sb, (kt + 1) & 1, gbase, (kt + 1) * 64, khi, klo, vhi, vlo, tid);
            CP_COMMIT();
            asm volatile("cp.async.wait_group 1;" ::: "memory");
        } else {
            asm volatile("cp.async.wait_group 0;" ::: "memory");
        }
        __syncthreads();

        const uint32_t kb = sb + AT_KV0 + (kt & 1) * AT_STAGE;

        // ---- S = (0.125 Q) K^T, bf16x3 ----
        float s[8][4];
#pragma unroll
        for (int j = 0; j < 8; j++)
#pragma unroll
            for (int r = 0; r < 4; r++) s[j][r] = 0.0f;

#pragma unroll
        for (int ks = 0; ks < 4; ks++) {
#pragma unroll
            for (int ng = 0; ng < 4; ng++) {
                uint32_t sw = SMEM_SWIZZLE_128B(
                    (uint32_t)((ng * 16 + brow) * 128 + (ks * 2 + bkc) * 16));
                uint32_t kh4[4], kl4[4];
                ldm_x4(kh4, kb + 0 + sw);
                ldm_x4(kl4, kb + 8192 + sw);
                mma16816(s[ng * 2],     qh[ks], kh4 + 0);
                mma16816(s[ng * 2],     qh[ks], kl4 + 0);
                mma16816(s[ng * 2],     ql[ks], kh4 + 0);
                mma16816(s[ng * 2 + 1], qh[ks], kh4 + 2);
                mma16816(s[ng * 2 + 1], qh[ks], kl4 + 2);
                mma16816(s[ng * 2 + 1], ql[ks], kh4 + 2);
            }
        }

        // ---- causal mask (diag tile only) ----
        if (kt == qt) {
            const int rlo = wid * 16 + (lid >> 2);
#pragma unroll
            for (int j = 0; j < 8; j++) {
                const int cb = ((j >> 1) << 4) + ((j & 1) << 3) + ((lid & 3) << 1);
                if (cb     > rlo)     s[j][0] = -1e30f;
                if (cb + 1 > rlo)     s[j][1] = -1e30f;
                if (cb     > rlo + 8) s[j][2] = -1e30f;
                if (cb + 1 > rlo + 8) s[j][3] = -1e30f;
            }
        }

        // ---- online softmax (FMA-pipe exp) ----
        float mx0 = -1e30f, mx1 = -1e30f;
#pragma unroll
        for (int j = 0; j < 8; j++) {
            mx0 = fmaxf(mx0, fmaxf(s[j][0], s[j][1]));
            mx1 = fmaxf(mx1, fmaxf(s[j][2], s[j][3]));
        }
        mx0 = fmaxf(mx0, __shfl_xor_sync(0xffffffffu, mx0, 1));
        mx0 = fmaxf(mx0, __shfl_xor_sync(0xffffffffu, mx0, 2));
        mx1 = fmaxf(mx1, __shfl_xor_sync(0xffffffffu, mx1, 1));
        mx1 = fmaxf(mx1, __shfl_xor_sync(0xffffffffu, mx1, 2));
        const float mn0 = fmaxf(m_run[0], mx0);
        const float mn1 = fmaxf(m_run[1], mx1);
        const float cr0 = exp_fast(m_run[0] - mn0);
        const float cr1 = exp_fast(m_run[1] - mn1);
        m_run[0] = mn0; m_run[1] = mn1;

        float ps0 = 0.0f, ps1 = 0.0f;
#pragma unroll
        for (int j = 0; j < 8; j++) {
            s[j][0] = exp_fast(s[j][0] - mn0); ps0 += s[j][0];
            s[j][1] = exp_fast(s[j][1] - mn0); ps0 += s[j][1];
            s[j][2] = exp_fast(s[j][2] - mn1); ps1 += s[j][2];
            s[j][3] = exp_fast(s[j][3] - mn1); ps1 += s[j][3];
        }
        ps0 += __shfl_xor_sync(0xffffffffu, ps0, 1);
        ps0 += __shfl_xor_sync(0xffffffffu, ps0, 2);
        ps1 += __shfl_xor_sync(0xffffffffu, ps1, 1);
        ps1 += __shfl_xor_sync(0xffffffffu, ps1, 2);
        l_run[0] = l_run[0] * cr0 + ps0;
        l_run[1] = l_run[1] * cr1 + ps1;

#pragma unroll
        for (int j = 0; j < 8; j++) {
            o[j][0] *= cr0; o[j][1] *= cr0;
            o[j][2] *= cr1; o[j][3] *= cr1;
        }

        // ---- P -> bf16 hi/lo A-fragments (in-register C->A remap) ----
        uint32_t ph[4][4], pl[4][4];
#pragma unroll
        for (int kc = 0; kc < 4; kc++) {
            hilo_pack(s[2 * kc][0],     s[2 * kc][1],     ph[kc][0], pl[kc][0]);
            hilo_pack(s[2 * kc][2],     s[2 * kc][3],     ph[kc][1], pl[kc][1]);
            hilo_pack(s[2 * kc + 1][0], s[2 * kc + 1][1], ph[kc][2], pl[kc][2]);
            hilo_pack(s[2 * kc + 1][2], s[2 * kc + 1][3], ph[kc][3], pl[kc][3]);
        }

        // ---- O += P V, bf16x3, V via ldmatrix.trans ----
        const uint32_t vb = kb + 16384;
#pragma unroll
        for (int kc = 0; kc < 4; kc++) {
#pragma unroll
            for (int nd = 0; nd < 4; nd++) {
                uint32_t sw = SMEM_SWIZZLE_128B(
                    (uint32_t)((kc * 16 + vrow) * 128 + (nd * 16 + vcol) * 2));
                uint32_t vh4[4], vl4[4];
                ldm_x4_t(vh4, vb + 0 + sw);
                ldm_x4_t(vl4, vb + 8192 + sw);
                mma16816(o[nd * 2],     ph[kc], vh4 + 0);
                mma16816(o[nd * 2],     ph[kc], vl4 + 0);
                mma16816(o[nd * 2],     pl[kc], vh4 + 0);
                mma16816(o[nd * 2 + 1], ph[kc], vh4 + 2);
                mma16816(o[nd * 2 + 1], ph[kc], vl4 + 2);
                mma16816(o[nd * 2 + 1], pl[kc], vh4 + 2);
            }
        }
    }

    // ---- epilogue: normalize, split to bf16 hi/lo, store ----
    const float inv0 = 1.0f / l_run[0];
    const float inv1 = 1.0f / l_run[1];
    const int rlo = q0 + wid * 16 + (lid >> 2);
#pragma unroll
    for (int j = 0; j < 8; j++) {
        const int col = ((j >> 1) << 4) + ((j & 1) << 3) + ((lid & 3) << 1);
        uint32_t hi, lo;
        size_t adr0 = gbase + (size_t)rlo * D_ + col;
        hilo_pack(o[j][0] * inv0, o[j][1] * inv0, hi, lo);
        *(uint32_t*)(ohi + adr0) = hi;
        *(uint32_t*)(olo + adr0) = lo;
        size_t adr1 = adr0 + (size_t)8 * D_;
        hilo_pack(o[j][2] * inv1, o[j][3] * inv1, hi, lo);
        *(uint32_t*)(ohi + adr1) = hi;
        *(uint32_t*)(olo + adr1) = lo;
    }
}

// ============================ launch ============================
extern "C" void kernel_launch(void* const* d_in, const int* in_sizes, int n_in,
                              void* d_out, int out_size)
{
    const float* x   = (const float*)d_in[0];
    const float* Wq  = (const float*)d_in[1];
    const float* Wk  = (const float*)d_in[2];
    const float* Wv  = (const float*)d_in[3];
    const float* Wo  = (const float*)d_in[4];
    const int*   pos = (const int*)  d_in[5];
    float* out = (float*)d_out;

    float *q_ptr, *k_ptr, *v_ptr;
    cudaGetSymbolAddress((void**)&q_ptr, g_q);
    cudaGetSymbolAddress((void**)&k_ptr, g_k);
    cudaGetSymbolAddress((void**)&v_ptr, g_v);
    __nv_bfloat16 *xhi, *xlo, *whi, *wlo;
    __nv_bfloat16 *qhi, *qlo, *khi, *klo, *vhi, *vlo, *ohi, *olo;
    cudaGetSymbolAddress((void**)&xhi, g_xhi);
    cudaGetSymbolAddress((void**)&xlo, g_xlo);
    cudaGetSymbolAddress((void**)&whi, g_whi);
    cudaGetSymbolAddress((void**)&wlo, g_wlo);
    cudaGetSymbolAddress((void**)&qhi, g_qhi);
    cudaGetSymbolAddress((void**)&qlo, g_qlo);
    cudaGetSymbolAddress((void**)&khi, g_khi);
    cudaGetSymbolAddress((void**)&klo, g_klo);
    cudaGetSymbolAddress((void**)&vhi, g_vhi);
    cudaGetSymbolAddress((void**)&vlo, g_vlo);
    cudaGetSymbolAddress((void**)&ohi, g_ohi);
    cudaGetSymbolAddress((void**)&olo, g_olo);

    cudaFuncSetAttribute(gemm_mma_qkv, cudaFuncAttributeMaxDynamicSharedMemorySize, GT_SMEM_TOTAL);
    cudaFuncSetAttribute(gemm_mma_one, cudaFuncAttributeMaxDynamicSharedMemorySize, GT_SMEM_TOTAL);
    cudaFuncSetAttribute(attn_mma,     cudaFuncAttributeMaxDynamicSharedMemorySize, AT_SMEM);

    const int nx4 = BL_ * D_ / 4;
    const int nw4 = D_ * D_ / 4;

    split_bf16<<<nx4 / 256, 256>>>(x, xhi, xlo, nx4);
    split_bf16<<<nw4 / 256, 256>>>(Wq, whi + 0 * (size_t)D_ * D_, wlo + 0 * (size_t)D_ * D_, nw4);
    split_bf16<<<nw4 / 256, 256>>>(Wk, whi + 1 * (size_t)D_ * D_, wlo + 1 * (size_t)D_ * D_, nw4);
    split_bf16<<<nw4 / 256, 256>>>(Wv, whi + 2 * (size_t)D_ * D_, wlo + 2 * (size_t)D_ * D_, nw4);
    split_bf16<<<nw4 / 256, 256>>>(Wo, whi + 3 * (size_t)D_ * D_, wlo + 3 * (size_t)D_ * D_, nw4);

    dim3 qkv_grid(D_ / 128, BL_ / 128, 3);
    gemm_mma_qkv<<<qkv_grid, 256, GT_SMEM_TOTAL>>>(xhi, xlo, whi, wlo, q_ptr, k_ptr, v_ptr);

    rope_split<<<(BL_ * (D_ / 2)) / 256, 256>>>(q_ptr, k_ptr, pos, qhi, qlo, khi, klo);
    split_bf16<<<nx4 / 256, 256>>>(v_ptr, vhi, vlo, nx4);

    attn_mma<<<dim3(L_ / 64, H_, B_), 128, AT_SMEM>>>(qhi, qlo, khi, klo, vhi, vlo, ohi, olo);

    dim3 ggrid(D_ / 128, BL_ / 128);
    gemm_mma_one<<<ggrid, 256, GT_SMEM_TOTAL>>>(ohi, olo,
                                                whi + 3 * (size_t)D_ * D_,
                                                wlo + 3 * (size_t)D_ * D_, out);
}